// round 14
// baseline (speedup 1.0000x reference)
#include <cuda_runtime.h>
#include <cuda_fp16.h>
#include <cstdint>

// NearestEmbed: x (64,64,32,32) f32, emb (64,512) f32
// out f32 = [ quantized 4194304 | argmin 65536 (as float) ]
//
// R14: R6 (best measured, 128 regs no spills) + two state-neutral changes:
//  1) FULL unroll of the 64-nt loop (immediate LDS/norm addresses, no loop alu)
//  2) branch-free top-2 (R13-verified semantics, FMNMX/FSEL instead of branches)

#define THREADS 512            // 16 warps, warp owns 16 rows per tile
#define TILE_M 256
#define GRID 128
#define TILES_PER_CTA 2
#define EMB_D 64
#define EMB_K 512
#define HW 1024
#define MARGIN 0.04f

// smem layout (bytes)
#define SM_FRAGS 0                       // u32 frags[64 nt][4 ks][32 lane][2] = 64KB
#define SM_EMB   65536                   // f32 emb_s[64][512] = 128KB
#define SM_NORMS (SM_EMB + 131072)       // f32 [512] = 2KB
#define SM_WSM   (SM_NORMS + 2048)       // i32 [16 warps][16] = 1KB
#define SM_XS    (SM_WSM + 1024)         // f32 [16 warps][64] = 4KB
#define SM_TOTAL (SM_XS + 4096)

__device__ __forceinline__ uint32_t packh2(float a, float b) {
    __half2 h = __floats2half2_rn(a, b);
    return *reinterpret_cast<uint32_t*>(&h);
}

__device__ __forceinline__ void hmma16816(float& c0, float& c1, float& c2, float& c3,
                                          uint32_t a0, uint32_t a1, uint32_t a2, uint32_t a3,
                                          uint32_t b0, uint32_t b1) {
    asm volatile("mma.sync.aligned.m16n8k16.row.col.f32.f16.f16.f32 "
                 "{%0,%1,%2,%3}, {%4,%5,%6,%7}, {%8,%9}, {%0,%1,%2,%3};"
                 : "+f"(c0), "+f"(c1), "+f"(c2), "+f"(c3)
                 : "r"(a0), "r"(a1), "r"(a2), "r"(a3), "r"(b0), "r"(b1));
}

// Branch-free top-2 update with a pair of adjacent-code scores.
// Verified (R13, rel_err 0). Semantics identical to the branchy version:
//   if (s0<b1){b2=b1;b1=s0;k1=n0;} else b2=min(b2,s0);
//   if (s1<b1){b2=b1;b1=s1;k1=n0+1;} else b2=min(b2,s1);
__device__ __forceinline__ void top2_pair(float s0, float s1, int n0,
                                          float& b1, float& b2, int& k1) {
    float sm = fminf(s0, s1);
    float pm = fmaxf(s0, s1);
    bool swap = (s1 < s0);
    int  km = n0 + (swap ? 1 : 0);
    bool take = (sm < b1);
    float t1 = take ? b1 : b2;
    float t2 = take ? pm : sm;
    b2 = fminf(t1, fminf(b2, t2));
    b1 = take ? sm : b1;
    k1 = take ? km : k1;
}

__global__ __launch_bounds__(THREADS, 1)
void vq_hmma_kernel(const float* __restrict__ x,
                    const float* __restrict__ emb,
                    float* __restrict__ out_q,
                    float* __restrict__ out_idx)
{
    extern __shared__ char smem[];
    uint32_t* frags = reinterpret_cast<uint32_t*>(smem + SM_FRAGS);
    float*    emb_s = reinterpret_cast<float*>(smem + SM_EMB);
    float*    norms = reinterpret_cast<float*>(smem + SM_NORMS);

    const int tid  = threadIdx.x;
    const int warp = tid >> 5;
    const int lane = tid & 31;
    const int gidq = lane & 3;
    const int grp  = lane >> 2;

    int*   wsm = reinterpret_cast<int*>(smem + SM_WSM) + warp * 16;
    float* xs  = reinterpret_cast<float*>(smem + SM_XS) + warp * 64;

    // ---- Prologue (once per CTA) ----
    for (int i = tid; i < EMB_D * EMB_K; i += THREADS) emb_s[i] = emb[i];
    __syncthreads();

    for (int k = tid; k < EMB_K; k += THREADS) {
        float s = 0.f;
        #pragma unroll
        for (int d = 0; d < EMB_D; d++) {
            float v = emb_s[d * EMB_K + k];
            s = fmaf(v, v, s);
        }
        norms[k] = s;
    }
    // B fragments: frags[((nt*4+ks)*32 + lane)*2 + j]
    for (int f = tid; f < 64 * 4 * 32 * 2; f += THREADS) {
        int j  = f & 1;
        int ln = (f >> 1) & 31;
        int ks = (f >> 6) & 3;
        int nt = f >> 8;
        int n  = nt * 8 + (ln >> 2);
        int d0 = ks * 16 + 2 * (ln & 3) + 8 * j;
        frags[f] = packh2(emb_s[d0 * EMB_K + n], emb_s[(d0 + 1) * EMB_K + n]);
    }
    __syncthreads();   // warps fully independent afterwards

    for (int it = 0; it < TILES_PER_CTA; it++) {
        const int tile = blockIdx.x * TILES_PER_CTA + it;
        const int row_base = tile * TILE_M;
        const int b = row_base >> 10;
        const int hw_base = row_base & (HW - 1);
        const float* xb = x + (size_t)b * (EMB_D * HW) + hw_base;   // x(row,d)=xb[d*HW+row]
        const int wrow = warp * 16;

        // ---- A fragments: this warp's 16 rows ----
        const float* xw = xb + wrow;
        uint32_t A[4][4];
        {
            const int q2 = gidq * 2;
            #pragma unroll
            for (int ks = 0; ks < 4; ks++) {
                int d = ks * 16 + q2;
                A[ks][0] = packh2(xw[d * HW + grp],           xw[(d + 1) * HW + grp]);
                A[ks][1] = packh2(xw[d * HW + grp + 8],       xw[(d + 1) * HW + grp + 8]);
                A[ks][2] = packh2(xw[(d + 8) * HW + grp],     xw[(d + 9) * HW + grp]);
                A[ks][3] = packh2(xw[(d + 8) * HW + grp + 8], xw[(d + 9) * HW + grp + 8]);
            }
        }

        // ---- coarse scan over 64 n-tiles (FULL unroll: immediate addresses) ----
        const float INF = __int_as_float(0x7f800000);
        float b1a = INF, b2a = INF, b1b = INF, b2b = INF;
        int k1a = 0, k1b = 0;

        const uint2* fr2 = reinterpret_cast<const uint2*>(frags) + lane;
        const float2* nrp = reinterpret_cast<const float2*>(norms + gidq * 2);

        #pragma unroll
        for (int nt = 0; nt < 64; nt++) {
            uint2 q0 = fr2[nt * 128];
            uint2 q1 = fr2[nt * 128 + 32];
            uint2 q2 = fr2[nt * 128 + 64];
            uint2 q3 = fr2[nt * 128 + 96];

            float c0 = 0.f, c1 = 0.f, c2 = 0.f, c3 = 0.f;
            hmma16816(c0, c1, c2, c3, A[0][0], A[0][1], A[0][2], A[0][3], q0.x, q0.y);
            hmma16816(c0, c1, c2, c3, A[1][0], A[1][1], A[1][2], A[1][3], q1.x, q1.y);
            hmma16816(c0, c1, c2, c3, A[2][0], A[2][1], A[2][2], A[2][3], q2.x, q2.y);
            hmma16816(c0, c1, c2, c3, A[3][0], A[3][1], A[3][2], A[3][3], q3.x, q3.y);

            const int n0 = nt * 8 + gidq * 2;
            float2 nr = nrp[nt * 4];
            float s0 = fmaf(-2.f, c0, nr.x);
            float s1 = fmaf(-2.f, c1, nr.y);
            float s2 = fmaf(-2.f, c2, nr.x);
            float s3 = fmaf(-2.f, c3, nr.y);
            top2_pair(s0, s1, n0, b1a, b2a, k1a);
            top2_pair(s2, s3, n0, b1b, b2b, k1b);
        }

        // ---- merge across the 4 lanes of each row-group ----
        #pragma unroll
        for (int off = 1; off <= 2; off <<= 1) {
            float ob1 = __shfl_xor_sync(0xffffffffu, b1a, off);
            int   ok1 = __shfl_xor_sync(0xffffffffu, k1a, off);
            float ob2 = __shfl_xor_sync(0xffffffffu, b2a, off);
            float nb2 = fminf(fmaxf(b1a, ob1), fminf(b2a, ob2));
            bool take = (ob1 < b1a) || (ob1 == b1a && ok1 < k1a);
            b1a = take ? ob1 : b1a; k1a = take ? ok1 : k1a; b2a = nb2;

            float pb = __shfl_xor_sync(0xffffffffu, b1b, off);
            int   pk = __shfl_xor_sync(0xffffffffu, k1b, off);
            float pq = __shfl_xor_sync(0xffffffffu, b2b, off);
            float qb = fminf(fmaxf(b1b, pb), fminf(b2b, pq));
            bool tk = (pb < b1b) || (pb == b1b && pk < k1b);
            b1b = tk ? pb : b1b; k1b = tk ? pk : k1b; b2b = qb;
        }

        // ---- record winners, mark ambiguous rows (in-warp) ----
        bool own = (gidq == 0);
        if (own) {
            wsm[grp]     = k1a;
            wsm[grp + 8] = k1b;
        }
        uint32_t mA = __ballot_sync(0xffffffffu, own && (b2a - b1a <= MARGIN));
        uint32_t mB = __ballot_sync(0xffffffffu, own && (b2b - b1b <= MARGIN));
        __syncwarp();

        uint32_t amb = 0;
        #pragma unroll
        for (int g = 0; g < 8; g++) {
            amb |= ((mA >> (4 * g)) & 1u) << g;
            amb |= ((mB >> (4 * g)) & 1u) << (g + 8);
        }

        // ---- in-warp exact fp32 rescue for ambiguous rows (rare) ----
        while (amb) {
            int r = __ffs(amb) - 1;
            amb &= amb - 1;
            const float* xg = xb + wrow + r;
            xs[lane]      = xg[(size_t)lane * HW];
            xs[lane + 32] = xg[(size_t)(lane + 32) * HW];
            __syncwarp();
            float best = __int_as_float(0x7f800000);
            int bk = 0;
            #pragma unroll 1
            for (int j = 0; j < 16; j++) {
                int k = lane + 32 * j;
                float acc = 0.f;
                #pragma unroll 8
                for (int d = 0; d < EMB_D; d++)
                    acc = fmaf(xs[d], emb_s[d * EMB_K + k], acc);
                float sc = fmaf(-2.f, acc, norms[k]);
                if (sc < best) { best = sc; bk = k; }
            }
            #pragma unroll
            for (int off = 16; off >= 1; off >>= 1) {
                float os = __shfl_xor_sync(0xffffffffu, best, off);
                int   ok = __shfl_xor_sync(0xffffffffu, bk, off);
                bool take = (os < best) || (os == best && ok < bk);
                best = take ? os : best;
                bk = take ? ok : bk;
            }
            if (lane == 0) wsm[r] = bk;
            __syncwarp();
        }
        __syncwarp();

        // ---- in-warp outputs: this warp's 16 rows ----
        float* oq = out_q + (size_t)b * (EMB_D * HW) + hw_base + wrow;
        #pragma unroll 8
        for (int i = lane; i < 16 * EMB_D; i += 32) {
            int r = i & 15;
            int d = i >> 4;
            oq[(size_t)d * HW + r] = emb_s[d * EMB_K + wsm[r]];
        }
        if (lane < 16) out_idx[row_base + wrow + lane] = (float)wsm[lane];
        __syncwarp();
    }
}

extern "C" void kernel_launch(void* const* d_in, const int* in_sizes, int n_in,
                              void* d_out, int out_size)
{
    const float* x   = (const float*)d_in[0];   // 4194304 f32
    const float* emb = (const float*)d_in[1];   // 32768 f32
    float* out_q = (float*)d_out;
    float* out_i = (float*)d_out + (size_t)4194304;

    cudaFuncSetAttribute(vq_hmma_kernel,
                         cudaFuncAttributeMaxDynamicSharedMemorySize, SM_TOTAL);
    vq_hmma_kernel<<<GRID, THREADS, SM_TOTAL>>>(x, emb, out_q, out_i);
}